// round 11
// baseline (speedup 1.0000x reference)
#include <cuda_runtime.h>
#include <cuda_fp16.h>
#include <cstdint>

// Problem constants (fixed shapes)
#define K_DIM 4096
#define N_DIM 11008
#define M_DIM 8192
#define NPACK 1376   /* N/8 packed int32 columns */

// GEMM tiling: CTA 128x128x64, 16 warps (4x4), warp tile 32x32, 512 threads,
// 3-stage cp.async, fp16-accumulate mma chained over k32 then promoted to fp32.
#define BM 128
#define BN 128
#define BK 64
#define NT 512
#define NSTAGE 3
#define SA_STRIDE 72    /* halves per A row (144B), conflict-free ldmatrix */
#define SB_STRIDE 136   /* halves per B row (272B), conflict-free ldmatrix */
#define SA_STAGE_HALVES (BM * SA_STRIDE)   /* 9216  -> 18432 B */
#define SB_STAGE_HALVES (BK * SB_STRIDE)   /* 8704  -> 17408 B */
#define KT_ITERS (K_DIM / BK)              /* 64 */

// Scratch (static __device__ arrays: allowed)
__device__ __half g_W[(size_t)K_DIM * N_DIM];   // 90 MB dequantized weights (fp16, [K,N])
__device__ __half g_X[(size_t)M_DIM * K_DIM];   // 64 MB activations fp32->fp16

#define CP_ASYNC_CG(dst, src) \
    asm volatile("cp.async.cg.shared.global [%0], [%1], 16;\n" :: "r"(dst), "l"(src))
#define CP_COMMIT() asm volatile("cp.async.commit_group;\n" ::)
#define CP_WAIT(n)  asm volatile("cp.async.wait_group %0;\n" :: "n"(n))

// ---------------------------------------------------------------------------
// Kernel 0: convert x (fp32 from harness) -> fp16 g_X. 8 elements/thread.
// ---------------------------------------------------------------------------
__global__ void convert_x_kernel(const float* __restrict__ x)
{
    size_t i = ((size_t)blockIdx.x * blockDim.x + threadIdx.x) * 8;
    if (i >= (size_t)M_DIM * K_DIM) return;
    float4 f0 = *reinterpret_cast<const float4*>(x + i);
    float4 f1 = *reinterpret_cast<const float4*>(x + i + 4);
    __half h[8];
    h[0] = __float2half(f0.x); h[1] = __float2half(f0.y);
    h[2] = __float2half(f0.z); h[3] = __float2half(f0.w);
    h[4] = __float2half(f1.x); h[5] = __float2half(f1.y);
    h[6] = __float2half(f1.z); h[7] = __float2half(f1.w);
    *reinterpret_cast<uint4*>(&g_X[i]) = *reinterpret_cast<uint4*>(h);
}

// ---------------------------------------------------------------------------
// Kernel 1: AWQ 4-bit dequant -> fp16 g_W[k][n] (nibble order {0,4,1,5,2,6,3,7})
// ---------------------------------------------------------------------------
__global__ void dequant_kernel(const int* __restrict__ qw,
                               const int* __restrict__ qz,
                               const float* __restrict__ sc)
{
    int idx = blockIdx.x * blockDim.x + threadIdx.x;
    if (idx >= K_DIM * NPACK) return;
    int k = idx / NPACK;
    int p = idx - k * NPACK;

    int w = qw[idx];
    int z = qz[(k >> 7) * NPACK + p];

    const float* sp = sc + (size_t)(k >> 7) * N_DIM + p * 8;
    float4 s0 = *reinterpret_cast<const float4*>(sp);
    float4 s1 = *reinterpret_cast<const float4*>(sp + 4);
    float sf[8] = {s0.x, s0.y, s0.z, s0.w, s1.x, s1.y, s1.z, s1.w};

    const int shift[8] = {0, 16, 4, 20, 8, 24, 12, 28};
    __half outv[8];
#pragma unroll
    for (int j = 0; j < 8; j++) {
        int iw = (w >> shift[j]) & 15;
        int iz = (z >> shift[j]) & 15;
        outv[j] = __float2half((float)(iw - iz) * sf[j]);
    }
    *reinterpret_cast<uint4*>(&g_W[(size_t)k * N_DIM + p * 8]) =
        *reinterpret_cast<uint4*>(outv);
}

// ---------------------------------------------------------------------------
// Kernel 2: fp16 mma.sync GEMM with FP16 ACCUMULATION chained over k32,
// promoted to fp32 registers every 2 mma steps. Fused bias, fp32 output.
// 128x128x64 CTA tile, 16 warps (4x4), warp tile 32x32, 3-stage cp.async,
// one __syncthreads per K-chunk.
// ---------------------------------------------------------------------------
__global__ void __launch_bounds__(NT, 1)
gemm_kernel(const float* __restrict__ bias, float* __restrict__ out)
{
    extern __shared__ __half dsm[];
    __half* sA = dsm;                                    // [NSTAGE][BM][SA_STRIDE]
    __half* sB = dsm + NSTAGE * SA_STAGE_HALVES;         // [NSTAGE][BK][SB_STRIDE]

    const int tid  = threadIdx.x;
    const int wid  = tid >> 5;
    const int lane = tid & 31;
    const int bm0  = blockIdx.x * BM;
    const int bn0  = blockIdx.y * BN;

    const int wm = (wid >> 2) * 32;   // warp row offset (4 groups of 32)
    const int wn = (wid & 3) * 32;    // warp col offset (4 groups of 32)

    float acc[2][4][4];
#pragma unroll
    for (int i = 0; i < 2; i++)
#pragma unroll
        for (int j = 0; j < 4; j++)
#pragma unroll
            for (int r = 0; r < 4; r++) acc[i][j][r] = 0.f;

    const __half* gA = g_X + (size_t)bm0 * K_DIM;
    const __half* gB = g_W + bn0;

    // Loader: A = 1024 16B-chunks (row=c>>3, k8=c&7); B = 1024 (row=d>>4, n8=d&15)
#define ISSUE_STAGE(buf, kt_)                                                        \
    do {                                                                             \
        const int kk = (kt_) * BK;                                                   \
        __half* aS = sA + (buf) * SA_STAGE_HALVES;                                   \
        __half* bS = sB + (buf) * SB_STAGE_HALVES;                                   \
        _Pragma("unroll")                                                            \
        for (int i = 0; i < 2; i++) {                                                \
            int c = tid + i * NT;                                                    \
            int row = c >> 3, k8 = c & 7;                                            \
            uint32_t dst = (uint32_t)__cvta_generic_to_shared(                       \
                aS + row * SA_STRIDE + k8 * 8);                                      \
            CP_ASYNC_CG(dst, gA + (size_t)row * K_DIM + kk + k8 * 8);                \
        }                                                                            \
        _Pragma("unroll")                                                            \
        for (int i = 0; i < 2; i++) {                                                \
            int d = tid + i * NT;                                                    \
            int row = d >> 4, n8 = d & 15;                                           \
            uint32_t dst = (uint32_t)__cvta_generic_to_shared(                       \
                bS + row * SB_STRIDE + n8 * 8);                                      \
            CP_ASYNC_CG(dst, gB + (size_t)(kk + row) * N_DIM + n8 * 8);              \
        }                                                                            \
        CP_COMMIT();                                                                 \
    } while (0)

    // Load frags for k16-step ks_: A 2x ldmatrix.x4 (rows wm..wm+31),
    // B 2x ldmatrix.x4.trans (cols wn..wn+31).
#define LOAD_FRAGS(ks_)                                                              \
    do {                                                                             \
        const int k16 = (ks_) * 16;                                                  \
        _Pragma("unroll")                                                            \
        for (int mi = 0; mi < 2; mi++) {                                             \
            uint32_t addr = (uint32_t)__cvta_generic_to_shared(                      \
                aS + (wm + mi * 16 + (lane & 15)) * SA_STRIDE + k16 + 8 * (lane >> 4)); \
            asm volatile(                                                            \
                "ldmatrix.sync.aligned.m8n8.x4.shared.b16 {%0,%1,%2,%3}, [%4];"      \
                : "=r"(fa[mi][0]), "=r"(fa[mi][1]),                                  \
                  "=r"(fa[mi][2]), "=r"(fa[mi][3])                                   \
                : "r"(addr));                                                        \
        }                                                                            \
        _Pragma("unroll")                                                            \
        for (int nj = 0; nj < 2; nj++) {                                             \
            uint32_t t0, t1, t2, t3;                                                 \
            uint32_t addr = (uint32_t)__cvta_generic_to_shared(                      \
                bS + (k16 + (lane & 15)) * SB_STRIDE + wn + nj * 16 + 8 * (lane >> 4)); \
            asm volatile(                                                            \
                "ldmatrix.sync.aligned.m8n8.x4.trans.shared.b16 {%0,%1,%2,%3}, [%4];"\
                : "=r"(t0), "=r"(t1), "=r"(t2), "=r"(t3)                             \
                : "r"(addr));                                                        \
            fb[nj * 2 + 0][0] = t0; fb[nj * 2 + 0][1] = t1;                          \
            fb[nj * 2 + 1][0] = t2; fb[nj * 2 + 1][1] = t3;                          \
        }                                                                            \
    } while (0)

// fp16-accumulate mma: D,C are 2 regs (4 halves)
#define MMA_F16(d0, d1, A, B, c0, c1)                                                \
    asm volatile(                                                                    \
        "mma.sync.aligned.m16n8k16.row.col.f16.f16.f16.f16 "                         \
        "{%0,%1}, {%2,%3,%4,%5}, {%6,%7}, {%8,%9};"                                  \
        : "=r"(d0), "=r"(d1)                                                         \
        : "r"((A)[0]), "r"((A)[1]), "r"((A)[2]), "r"((A)[3]),                        \
          "r"((B)[0]), "r"((B)[1]), "r"(c0), "r"(c1))

    // Prologue: prefetch stages 0,1
    ISSUE_STAGE(0, 0);
    ISSUE_STAGE(1, 1);

    uint32_t fa[2][4];
    uint32_t fb[4][2];
    uint32_t dH[2][4][2];   // fp16 running accum for the current k32 chain

    for (int kt = 0; kt < KT_ITERS; kt++) {
        const int s = kt % 3;
        if (kt + 2 < KT_ITERS) CP_WAIT(1);
        else                   CP_WAIT(0);
        __syncthreads();   // stage kt visible; all warps done with buffer being refilled
        if (kt + 2 < KT_ITERS) ISSUE_STAGE((kt + 2) % 3, kt + 2);

        const __half* aS = sA + s * SA_STAGE_HALVES;
        const __half* bS = sB + s * SB_STAGE_HALVES;

#pragma unroll
        for (int ksp = 0; ksp < 2; ksp++) {
            // k16 step 1 of the chain: fresh fp16 accumulator (C = 0)
            LOAD_FRAGS(2 * ksp);
#pragma unroll
            for (int mi = 0; mi < 2; mi++)
#pragma unroll
                for (int ni = 0; ni < 4; ni++)
                    MMA_F16(dH[mi][ni][0], dH[mi][ni][1], fa[mi], fb[ni], 0u, 0u);
            // k16 step 2: chain in fp16
            LOAD_FRAGS(2 * ksp + 1);
#pragma unroll
            for (int mi = 0; mi < 2; mi++)
#pragma unroll
                for (int ni = 0; ni < 4; ni++)
                    MMA_F16(dH[mi][ni][0], dH[mi][ni][1], fa[mi], fb[ni],
                            dH[mi][ni][0], dH[mi][ni][1]);
            // promote k32 partial to fp32
#pragma unroll
            for (int mi = 0; mi < 2; mi++)
#pragma unroll
                for (int ni = 0; ni < 4; ni++) {
                    float2 lo = __half22float2(*reinterpret_cast<__half2*>(&dH[mi][ni][0]));
                    float2 hi = __half22float2(*reinterpret_cast<__half2*>(&dH[mi][ni][1]));
                    acc[mi][ni][0] += lo.x; acc[mi][ni][1] += lo.y;
                    acc[mi][ni][2] += hi.x; acc[mi][ni][3] += hi.y;
                }
        }
    }

    // Epilogue: fp32 acc + fp32 bias -> fp16 round -> fp32 output, float2 stores
#pragma unroll
    for (int mi = 0; mi < 2; mi++) {
        int row0 = bm0 + wm + mi * 16 + (lane >> 2);
#pragma unroll
        for (int ni = 0; ni < 4; ni++) {
            int col = bn0 + wn + ni * 8 + (lane & 3) * 2;
            float2 bb = *reinterpret_cast<const float2*>(bias + col);
            float r00 = __half2float(__float2half(acc[mi][ni][0] + bb.x));
            float r01 = __half2float(__float2half(acc[mi][ni][1] + bb.y));
            float r10 = __half2float(__float2half(acc[mi][ni][2] + bb.x));
            float r11 = __half2float(__float2half(acc[mi][ni][3] + bb.y));
            *reinterpret_cast<float2*>(out + (size_t)row0 * N_DIM + col) =
                make_float2(r00, r01);
            *reinterpret_cast<float2*>(out + (size_t)(row0 + 8) * N_DIM + col) =
                make_float2(r10, r11);
        }
    }
}

// ---------------------------------------------------------------------------
// Inputs (metadata order): x fp32, qweight int32, qzeros int32, scales fp32,
// bias fp32. Output fp32 (harness transports fp16 tensors as float32).
// ---------------------------------------------------------------------------
extern "C" void kernel_launch(void* const* d_in, const int* in_sizes, int n_in,
                              void* d_out, int out_size)
{
    const float* x    = (const float*)d_in[0];
    const int*   qw   = (const int*)d_in[1];
    const int*   qz   = (const int*)d_in[2];
    const float* sc   = (const float*)d_in[3];
    const float* bias = (const float*)d_in[4];
    float*       out  = (float*)d_out;

    const size_t xtotal = (size_t)M_DIM * K_DIM;
    convert_x_kernel<<<(unsigned)((xtotal / 8 + 255) / 256), 256>>>(x);

    const int total = K_DIM * NPACK;
    dequant_kernel<<<(total + 255) / 256, 256>>>(qw, qz, sc);

    const int smem_bytes =
        (NSTAGE * SA_STAGE_HALVES + NSTAGE * SB_STAGE_HALVES) * (int)sizeof(__half);
    cudaFuncSetAttribute(gemm_kernel,
                         cudaFuncAttributeMaxDynamicSharedMemorySize, smem_bytes);
    dim3 grid(M_DIM / BM, N_DIM / BN);   // (64, 86)
    gemm_kernel<<<grid, NT, smem_bytes>>>(bias, out);
}

// round 13
// speedup vs baseline: 1.3733x; 1.3733x over previous
#include <cuda_runtime.h>
#include <cuda_fp16.h>
#include <cstdint>

// Problem constants (fixed shapes)
#define K_DIM 4096
#define N_DIM 11008
#define M_DIM 8192
#define NPACK 1376   /* N/8 packed int32 columns */

// GEMM tiling: CTA 128x128x64, 8 warps (2x4), warp tile 64x32 (R6 geometry),
// 3-stage A via cp.async, B dequantized IN-KERNEL from cp.async-staged raw
// quant data (2-deep raw staging + 2-deep B fp16 tile).
#define BM 128
#define BN 128
#define BK 64
#define NSTAGE_A 3
#define SA_STRIDE 72    /* halves per A row (144B), conflict-free ldmatrix */
#define SB_STRIDE 136   /* halves per B row (272B), conflict-free ldmatrix */
#define SA_STAGE_HALVES (BM * SA_STRIDE)   /* 9216 halves -> 18432 B */
#define SB_STAGE_HALVES (BK * SB_STRIDE)   /* 8704 halves -> 17408 B */
#define KT_ITERS (K_DIM / BK)              /* 64 */

// smem byte offsets
#define SA_BYTES   (NSTAGE_A * SA_STAGE_HALVES * 2)   /* 55296 */
#define SBT_OFF    SA_BYTES
#define SBT_BYTES  (2 * SB_STAGE_HALVES * 2)          /* 34816 */
#define RAW_OFF    (SBT_OFF + SBT_BYTES)              /* 90112 */
#define RAW_BYTES  4672   /* qw 4096 + qz 64 + sc(fp32) 512 */
#define SMEM_TOTAL (RAW_OFF + 2 * RAW_BYTES)          /* 99456 */

// Scratch (static __device__ array: allowed)
__device__ __half g_X[(size_t)M_DIM * K_DIM];   // 64 MB activations fp32->fp16

#define CP_ASYNC_CG(dst, src) \
    asm volatile("cp.async.cg.shared.global [%0], [%1], 16;\n" :: "r"(dst), "l"(src))
#define CP_COMMIT() asm volatile("cp.async.commit_group;\n" ::)
#define CP_WAIT(n)  asm volatile("cp.async.wait_group %0;\n" :: "n"(n))

__device__ __forceinline__ uint32_t h2_bits(__half2 h) {
    uint32_t u;
    *reinterpret_cast<__half2*>(&u) = h;
    return u;
}

// ---------------------------------------------------------------------------
// Kernel 0: convert x (fp32 from harness) -> fp16 g_X. 8 elements/thread.
// ---------------------------------------------------------------------------
__global__ void convert_x_kernel(const float* __restrict__ x)
{
    size_t i = ((size_t)blockIdx.x * blockDim.x + threadIdx.x) * 8;
    if (i >= (size_t)M_DIM * K_DIM) return;
    float4 f0 = *reinterpret_cast<const float4*>(x + i);
    float4 f1 = *reinterpret_cast<const float4*>(x + i + 4);
    __half h[8];
    h[0] = __float2half(f0.x); h[1] = __float2half(f0.y);
    h[2] = __float2half(f0.z); h[3] = __float2half(f0.w);
    h[4] = __float2half(f1.x); h[5] = __float2half(f1.y);
    h[6] = __float2half(f1.z); h[7] = __float2half(f1.w);
    *reinterpret_cast<uint4*>(&g_X[i]) = *reinterpret_cast<uint4*>(h);
}

// ---------------------------------------------------------------------------
// Kernel 1: fused AWQ-dequant + fp16 mma.sync GEMM, fp32 accum, fused bias.
// ---------------------------------------------------------------------------
__global__ void __launch_bounds__(256, 2)
gemm_kernel(const int* __restrict__ qweight,
            const int* __restrict__ qzeros,
            const float* __restrict__ sc32,
            const float* __restrict__ bias,
            float* __restrict__ out)
{
    extern __shared__ char dsm[];
    __half* sA  = reinterpret_cast<__half*>(dsm);                 // 3-deep A tiles
    __half* sBt = reinterpret_cast<__half*>(dsm + SBT_OFF);       // 2-deep B fp16 tiles
    char*   raw = dsm + RAW_OFF;                                  // 2-deep raw staging

    const int tid  = threadIdx.x;
    const int wid  = tid >> 5;
    const int lane = tid & 31;
    const int bm0  = blockIdx.x * BM;
    const int bn0  = blockIdx.y * BN;
    const int P0   = bn0 >> 3;   // packed-column base

    const int wm = (wid >> 2) * 64;   // warp row offset
    const int wn = (wid & 3) * 32;    // warp col offset

    float acc[4][4][4];
#pragma unroll
    for (int i = 0; i < 4; i++)
#pragma unroll
        for (int j = 0; j < 4; j++)
#pragma unroll
            for (int r = 0; r < 4; r++) acc[i][j][r] = 0.f;

    const __half* gA = g_X + (size_t)bm0 * K_DIM;

    // Issue cp.async group for stage st: A tile + raw B quant data.
#define ISSUE_GROUP(st_)                                                             \
    do {                                                                             \
        const int kk = (st_) * BK;                                                   \
        __half* aS = sA + ((st_) % 3) * SA_STAGE_HALVES;                             \
        _Pragma("unroll")                                                            \
        for (int i = 0; i < 4; i++) {                                                \
            int c = tid + i * 256;                                                   \
            int row = c >> 3, k8 = c & 7;                                            \
            uint32_t dst = (uint32_t)__cvta_generic_to_shared(                       \
                aS + row * SA_STRIDE + k8 * 8);                                      \
            CP_ASYNC_CG(dst, gA + (size_t)row * K_DIM + kk + k8 * 8);                \
        }                                                                            \
        char* rb = raw + ((st_) % 2) * RAW_BYTES;                                    \
        {   /* qw: 256 x 16B chunks, one per thread */                               \
            int row = tid >> 2, quad = tid & 3;                                      \
            uint32_t dst = (uint32_t)__cvta_generic_to_shared(rb + tid * 16);        \
            CP_ASYNC_CG(dst, qweight + (size_t)(kk + row) * NPACK + P0 + 4 * quad);  \
        }                                                                            \
        const int g_ = (st_) >> 1;                                                   \
        if (tid < 4) {  /* qz: 64B */                                                \
            uint32_t dst = (uint32_t)__cvta_generic_to_shared(rb + 4096 + tid * 16); \
            CP_ASYNC_CG(dst, qzeros + (size_t)g_ * NPACK + P0 + 4 * tid);            \
        }                                                                            \
        if (tid < 32) { /* scales fp32: 512B */                                      \
            uint32_t dst = (uint32_t)__cvta_generic_to_shared(rb + 4160 + tid * 16); \
            CP_ASYNC_CG(dst, sc32 + (size_t)g_ * N_DIM + bn0 + 4 * tid);             \
        }                                                                            \
        CP_COMMIT();                                                                 \
    } while (0)

    // Dequant stage st: raw[(st)%2] -> sBt[(st)%2]. Nibble order {0,16,4,20,8,24,12,28}.
#define DEQUANT(st_)                                                                 \
    do {                                                                             \
        const char* rb = raw + ((st_) % 2) * RAW_BYTES;                              \
        __half* bT = sBt + ((st_) % 2) * SB_STAGE_HALVES;                            \
        const int n8 = tid & 15, r0 = tid >> 4;                                      \
        int qz = *reinterpret_cast<const int*>(rb + 4096 + n8 * 4);                  \
        float4 s0 = *reinterpret_cast<const float4*>(rb + 4160 + n8 * 32);           \
        float4 s1 = *reinterpret_cast<const float4*>(rb + 4160 + n8 * 32 + 16);      \
        float sf[8] = {s0.x, s0.y, s0.z, s0.w, s1.x, s1.y, s1.z, s1.w};              \
        const int sh[8] = {0, 16, 4, 20, 8, 24, 12, 28};                             \
        int z[8];                                                                    \
        _Pragma("unroll")                                                            \
        for (int j = 0; j < 8; j++) z[j] = (qz >> sh[j]) & 15;                       \
        _Pragma("unroll")                                                            \
        for (int i = 0; i < 4; i++) {                                                \
            int row = r0 + 16 * i;                                                   \
            int w = *reinterpret_cast<const int*>(rb + (row * 16 + n8) * 4);         \
            float v[8];                                                              \
            _Pragma("unroll")                                                        \
            for (int j = 0; j < 8; j++)                                              \
                v[j] = (float)(((w >> sh[j]) & 15) - z[j]) * sf[j];                  \
            uint4 pk;                                                                \
            pk.x = h2_bits(__floats2half2_rn(v[0], v[1]));                           \
            pk.y = h2_bits(__floats2half2_rn(v[2], v[3]));                           \
            pk.z = h2_bits(__floats2half2_rn(v[4], v[5]));                           \
            pk.w = h2_bits(__floats2half2_rn(v[6], v[7]));                           \
            *reinterpret_cast<uint4*>(bT + row * SB_STRIDE + n8 * 8) = pk;           \
        }                                                                            \
    } while (0)

    // Prologue
    ISSUE_GROUP(0);
    ISSUE_GROUP(1);
    CP_WAIT(1);        // group 0 complete
    __syncthreads();   // cross-thread visibility of raw[0]
    DEQUANT(0);

    for (int kt = 0; kt < KT_ITERS; kt++) {
        __syncthreads();   // sync1: protects raw/sA/sBt buffer reuse
        if (kt + 2 < KT_ITERS) ISSUE_GROUP(kt + 2);
        if (kt < KT_ITERS - 2) CP_WAIT(1);
        else                   CP_WAIT(0);
        __syncthreads();   // sync2: cross-thread visibility of group kt+1
        if (kt + 1 < KT_ITERS) DEQUANT(kt + 1);

        const __half* aS = sA + (kt % 3) * SA_STAGE_HALVES;
        const __half* bT = sBt + (kt % 2) * SB_STAGE_HALVES;

#pragma unroll
        for (int ks = 0; ks < 4; ks++) {
            const int k16 = ks * 16;
            uint32_t a[4][4];
#pragma unroll
            for (int mi = 0; mi < 4; mi++) {
                uint32_t addr = (uint32_t)__cvta_generic_to_shared(
                    aS + (wm + mi * 16 + (lane & 15)) * SA_STRIDE + k16 + 8 * (lane >> 4));
                asm volatile(
                    "ldmatrix.sync.aligned.m8n8.x4.shared.b16 {%0,%1,%2,%3}, [%4];"
                    : "=r"(a[mi][0]), "=r"(a[mi][1]), "=r"(a[mi][2]), "=r"(a[mi][3])
                    : "r"(addr));
            }
            uint32_t b[4][2];
#pragma unroll
            for (int nj = 0; nj < 2; nj++) {
                uint32_t t0, t1, t2, t3;
                uint32_t addr = (uint32_t)__cvta_generic_to_shared(
                    bT + (k16 + (lane & 15)) * SB_STRIDE + wn + nj * 16 + 8 * (lane >> 4));
                asm volatile(
                    "ldmatrix.sync.aligned.m8n8.x4.trans.shared.b16 {%0,%1,%2,%3}, [%4];"
                    : "=r"(t0), "=r"(t1), "=r"(t2), "=r"(t3)
                    : "r"(addr));
                b[nj * 2 + 0][0] = t0; b[nj * 2 + 0][1] = t1;
                b[nj * 2 + 1][0] = t2; b[nj * 2 + 1][1] = t3;
            }
#pragma unroll
            for (int mi = 0; mi < 4; mi++)
#pragma unroll
                for (int ni = 0; ni < 4; ni++) {
                    asm volatile(
                        "mma.sync.aligned.m16n8k16.row.col.f32.f16.f16.f32 "
                        "{%0,%1,%2,%3}, {%4,%5,%6,%7}, {%8,%9}, {%0,%1,%2,%3};"
                        : "+f"(acc[mi][ni][0]), "+f"(acc[mi][ni][1]),
                          "+f"(acc[mi][ni][2]), "+f"(acc[mi][ni][3])
                        : "r"(a[mi][0]), "r"(a[mi][1]), "r"(a[mi][2]), "r"(a[mi][3]),
                          "r"(b[ni][0]), "r"(b[ni][1]));
                }
        }
    }

    // Epilogue: fp32 acc + fp32 bias -> fp16 round -> fp32 output, float2 stores
#pragma unroll
    for (int mi = 0; mi < 4; mi++) {
        int row0 = bm0 + wm + mi * 16 + (lane >> 2);
#pragma unroll
        for (int ni = 0; ni < 4; ni++) {
            int col = bn0 + wn + ni * 8 + (lane & 3) * 2;
            float2 bb = *reinterpret_cast<const float2*>(bias + col);
            float r00 = __half2float(__float2half(acc[mi][ni][0] + bb.x));
            float r01 = __half2float(__float2half(acc[mi][ni][1] + bb.y));
            float r10 = __half2float(__float2half(acc[mi][ni][2] + bb.x));
            float r11 = __half2float(__float2half(acc[mi][ni][3] + bb.y));
            *reinterpret_cast<float2*>(out + (size_t)row0 * N_DIM + col) =
                make_float2(r00, r01);
            *reinterpret_cast<float2*>(out + (size_t)(row0 + 8) * N_DIM + col) =
                make_float2(r10, r11);
        }
    }
}

// ---------------------------------------------------------------------------
// Inputs (metadata order): x fp32, qweight int32, qzeros int32, scales fp32,
// bias fp32. Output fp32 (harness transports fp16 tensors as float32).
// ---------------------------------------------------------------------------
extern "C" void kernel_launch(void* const* d_in, const int* in_sizes, int n_in,
                              void* d_out, int out_size)
{
    const float* x    = (const float*)d_in[0];
    const int*   qw   = (const int*)d_in[1];
    const int*   qz   = (const int*)d_in[2];
    const float* sc   = (const float*)d_in[3];
    const float* bias = (const float*)d_in[4];
    float*       out  = (float*)d_out;

    const size_t xtotal = (size_t)M_DIM * K_DIM;
    convert_x_kernel<<<(unsigned)((xtotal / 8 + 255) / 256), 256>>>(x);

    cudaFuncSetAttribute(gemm_kernel,
                         cudaFuncAttributeMaxDynamicSharedMemorySize, SMEM_TOTAL);
    dim3 grid(M_DIM / BM, N_DIM / BN);   // (64, 86)
    gemm_kernel<<<grid, 256, SMEM_TOTAL>>>(qw, qz, sc, bias, out);
}

// round 14
// speedup vs baseline: 1.5182x; 1.1055x over previous
#include <cuda_runtime.h>
#include <cuda_fp16.h>
#include <cstdint>

// Problem constants (fixed shapes)
#define K_DIM 4096
#define N_DIM 11008
#define M_DIM 8192
#define NPACK 1376   /* N/8 packed int32 columns */

// GEMM tiling: CTA 128x128x64, 16 warps (4x4), warp tile 32x32, 512 threads,
// 2 CTAs/SM (32 warps/SM), 3-stage cp.async, fp32-accum mma.
#define BM 128
#define BN 128
#define BK 64
#define NT 512
#define NSTAGE 3
#define SA_STRIDE 72    /* halves per A row (144B), conflict-free ldmatrix */
#define SB_STRIDE 136   /* halves per B row (272B), conflict-free ldmatrix */
#define SA_STAGE_HALVES (BM * SA_STRIDE)   /* 9216  -> 18432 B */
#define SB_STAGE_HALVES (BK * SB_STRIDE)   /* 8704  -> 17408 B */
#define KT_ITERS (K_DIM / BK)              /* 64 */

// Scratch (static __device__ arrays: allowed)
__device__ __half g_W[(size_t)K_DIM * N_DIM];   // 90 MB dequantized weights (fp16, [K,N])
__device__ __half g_X[(size_t)M_DIM * K_DIM];   // 64 MB activations fp32->fp16

#define CP_ASYNC_CG(dst, src) \
    asm volatile("cp.async.cg.shared.global [%0], [%1], 16;\n" :: "r"(dst), "l"(src))
#define CP_COMMIT() asm volatile("cp.async.commit_group;\n" ::)
#define CP_WAIT(n)  asm volatile("cp.async.wait_group %0;\n" :: "n"(n))

// ---------------------------------------------------------------------------
// Kernel 0: convert x (fp32 from harness) -> fp16 g_X. 8 elements/thread.
// ---------------------------------------------------------------------------
__global__ void convert_x_kernel(const float* __restrict__ x)
{
    size_t i = ((size_t)blockIdx.x * blockDim.x + threadIdx.x) * 8;
    if (i >= (size_t)M_DIM * K_DIM) return;
    float4 f0 = *reinterpret_cast<const float4*>(x + i);
    float4 f1 = *reinterpret_cast<const float4*>(x + i + 4);
    __half h[8];
    h[0] = __float2half(f0.x); h[1] = __float2half(f0.y);
    h[2] = __float2half(f0.z); h[3] = __float2half(f0.w);
    h[4] = __float2half(f1.x); h[5] = __float2half(f1.y);
    h[6] = __float2half(f1.z); h[7] = __float2half(f1.w);
    *reinterpret_cast<uint4*>(&g_X[i]) = *reinterpret_cast<uint4*>(h);
}

// ---------------------------------------------------------------------------
// Kernel 1: AWQ 4-bit dequant -> fp16 g_W[k][n] (nibble order {0,4,1,5,2,6,3,7})
// ---------------------------------------------------------------------------
__global__ void dequant_kernel(const int* __restrict__ qw,
                               const int* __restrict__ qz,
                               const float* __restrict__ sc)
{
    int idx = blockIdx.x * blockDim.x + threadIdx.x;
    if (idx >= K_DIM * NPACK) return;
    int k = idx / NPACK;
    int p = idx - k * NPACK;

    int w = qw[idx];
    int z = qz[(k >> 7) * NPACK + p];

    const float* sp = sc + (size_t)(k >> 7) * N_DIM + p * 8;
    float4 s0 = *reinterpret_cast<const float4*>(sp);
    float4 s1 = *reinterpret_cast<const float4*>(sp + 4);
    float sf[8] = {s0.x, s0.y, s0.z, s0.w, s1.x, s1.y, s1.z, s1.w};

    const int shift[8] = {0, 16, 4, 20, 8, 24, 12, 28};
    __half outv[8];
#pragma unroll
    for (int j = 0; j < 8; j++) {
        int iw = (w >> shift[j]) & 15;
        int iz = (z >> shift[j]) & 15;
        outv[j] = __float2half((float)(iw - iz) * sf[j]);
    }
    *reinterpret_cast<uint4*>(&g_W[(size_t)k * N_DIM + p * 8]) =
        *reinterpret_cast<uint4*>(outv);
}

// ---------------------------------------------------------------------------
// Kernel 2: fp16 mma.sync GEMM, fp32 accum, fused bias, fp32 output.
// 128x128x64 CTA tile, 512 threads, 16 warps (4x4) warp tile 32x32,
// 2 CTAs/SM => 32 warps/SM (occupancy 50%), 3-stage cp.async,
// one __syncthreads per K-chunk.
// ---------------------------------------------------------------------------
__global__ void __launch_bounds__(NT, 2)
gemm_kernel(const float* __restrict__ bias, float* __restrict__ out)
{
    extern __shared__ __half dsm[];
    __half* sA = dsm;                                    // [NSTAGE][BM][SA_STRIDE]
    __half* sB = dsm + NSTAGE * SA_STAGE_HALVES;         // [NSTAGE][BK][SB_STRIDE]

    const int tid  = threadIdx.x;
    const int wid  = tid >> 5;
    const int lane = tid & 31;
    const int bm0  = blockIdx.x * BM;
    const int bn0  = blockIdx.y * BN;

    const int wm = (wid >> 2) * 32;   // warp row offset (4 groups of 32)
    const int wn = (wid & 3) * 32;    // warp col offset (4 groups of 32)

    float acc[2][4][4];
#pragma unroll
    for (int i = 0; i < 2; i++)
#pragma unroll
        for (int j = 0; j < 4; j++)
#pragma unroll
            for (int r = 0; r < 4; r++) acc[i][j][r] = 0.f;

    const __half* gA = g_X + (size_t)bm0 * K_DIM;
    const __half* gB = g_W + bn0;

    // Loader: A = 1024 16B-chunks (row=c>>3, k8=c&7); B = 1024 (row=d>>4, n8=d&15)
#define ISSUE_STAGE(buf, kt_)                                                        \
    do {                                                                             \
        const int kk = (kt_) * BK;                                                   \
        __half* aS = sA + (buf) * SA_STAGE_HALVES;                                   \
        __half* bS = sB + (buf) * SB_STAGE_HALVES;                                   \
        _Pragma("unroll")                                                            \
        for (int i = 0; i < 2; i++) {                                                \
            int c = tid + i * NT;                                                    \
            int row = c >> 3, k8 = c & 7;                                            \
            uint32_t dst = (uint32_t)__cvta_generic_to_shared(                       \
                aS + row * SA_STRIDE + k8 * 8);                                      \
            CP_ASYNC_CG(dst, gA + (size_t)row * K_DIM + kk + k8 * 8);                \
        }                                                                            \
        _Pragma("unroll")                                                            \
        for (int i = 0; i < 2; i++) {                                                \
            int d = tid + i * NT;                                                    \
            int row = d >> 4, n8 = d & 15;                                           \
            uint32_t dst = (uint32_t)__cvta_generic_to_shared(                       \
                bS + row * SB_STRIDE + n8 * 8);                                      \
            CP_ASYNC_CG(dst, gB + (size_t)(kk + row) * N_DIM + n8 * 8);              \
        }                                                                            \
        CP_COMMIT();                                                                 \
    } while (0)

    // Prologue: prefetch stages 0,1
    ISSUE_STAGE(0, 0);
    ISSUE_STAGE(1, 1);

    for (int kt = 0; kt < KT_ITERS; kt++) {
        const int s = kt % 3;
        if (kt + 2 < KT_ITERS) CP_WAIT(1);
        else                   CP_WAIT(0);
        __syncthreads();   // stage kt visible; all warps done with buffer being refilled
        if (kt + 2 < KT_ITERS) ISSUE_STAGE((kt + 2) % 3, kt + 2);

        const __half* aS = sA + s * SA_STAGE_HALVES;
        const __half* bS = sB + s * SB_STAGE_HALVES;

#pragma unroll
        for (int ks = 0; ks < 4; ks++) {
            const int k16 = ks * 16;
            uint32_t a[2][4];
#pragma unroll
            for (int mi = 0; mi < 2; mi++) {
                uint32_t addr = (uint32_t)__cvta_generic_to_shared(
                    aS + (wm + mi * 16 + (lane & 15)) * SA_STRIDE + k16 + 8 * (lane >> 4));
                asm volatile(
                    "ldmatrix.sync.aligned.m8n8.x4.shared.b16 {%0,%1,%2,%3}, [%4];"
                    : "=r"(a[mi][0]), "=r"(a[mi][1]), "=r"(a[mi][2]), "=r"(a[mi][3])
                    : "r"(addr));
            }
            uint32_t b[4][2];
#pragma unroll
            for (int nj = 0; nj < 2; nj++) {
                uint32_t t0, t1, t2, t3;
                uint32_t addr = (uint32_t)__cvta_generic_to_shared(
                    bS + (k16 + (lane & 15)) * SB_STRIDE + wn + nj * 16 + 8 * (lane >> 4));
                asm volatile(
                    "ldmatrix.sync.aligned.m8n8.x4.trans.shared.b16 {%0,%1,%2,%3}, [%4];"
                    : "=r"(t0), "=r"(t1), "=r"(t2), "=r"(t3)
                    : "r"(addr));
                b[nj * 2 + 0][0] = t0; b[nj * 2 + 0][1] = t1;
                b[nj * 2 + 1][0] = t2; b[nj * 2 + 1][1] = t3;
            }
#pragma unroll
            for (int mi = 0; mi < 2; mi++)
#pragma unroll
                for (int ni = 0; ni < 4; ni++) {
                    asm volatile(
                        "mma.sync.aligned.m16n8k16.row.col.f32.f16.f16.f32 "
                        "{%0,%1,%2,%3}, {%4,%5,%6,%7}, {%8,%9}, {%0,%1,%2,%3};"
                        : "+f"(acc[mi][ni][0]), "+f"(acc[mi][ni][1]),
                          "+f"(acc[mi][ni][2]), "+f"(acc[mi][ni][3])
                        : "r"(a[mi][0]), "r"(a[mi][1]), "r"(a[mi][2]), "r"(a[mi][3]),
                          "r"(b[ni][0]), "r"(b[ni][1]));
                }
        }
    }

    // Epilogue: fp32 acc + fp32 bias -> fp16 round -> fp32 output, float2 stores
#pragma unroll
    for (int mi = 0; mi < 2; mi++) {
        int row0 = bm0 + wm + mi * 16 + (lane >> 2);
#pragma unroll
        for (int ni = 0; ni < 4; ni++) {
            int col = bn0 + wn + ni * 8 + (lane & 3) * 2;
            float2 bb = *reinterpret_cast<const float2*>(bias + col);
            float r00 = __half2float(__float2half(acc[mi][ni][0] + bb.x));
            float r01 = __half2float(__float2half(acc[mi][ni][1] + bb.y));
            float r10 = __half2float(__float2half(acc[mi][ni][2] + bb.x));
            float r11 = __half2float(__float2half(acc[mi][ni][3] + bb.y));
            *reinterpret_cast<float2*>(out + (size_t)row0 * N_DIM + col) =
                make_float2(r00, r01);
            *reinterpret_cast<float2*>(out + (size_t)(row0 + 8) * N_DIM + col) =
                make_float2(r10, r11);
        }
    }
}

// ---------------------------------------------------------------------------
// Inputs (metadata order): x fp32, qweight int32, qzeros int32, scales fp32,
// bias fp32. Output fp32 (harness transports fp16 tensors as float32).
// ---------------------------------------------------------------------------
extern "C" void kernel_launch(void* const* d_in, const int* in_sizes, int n_in,
                              void* d_out, int out_size)
{
    const float* x    = (const float*)d_in[0];
    const int*   qw   = (const int*)d_in[1];
    const int*   qz   = (const int*)d_in[2];
    const float* sc   = (const float*)d_in[3];
    const float* bias = (const float*)d_in[4];
    float*       out  = (float*)d_out;

    const size_t xtotal = (size_t)M_DIM * K_DIM;
    convert_x_kernel<<<(unsigned)((xtotal / 8 + 255) / 256), 256>>>(x);

    const int total = K_DIM * NPACK;
    dequant_kernel<<<(total + 255) / 256, 256>>>(qw, qz, sc);

    const int smem_bytes =
        (NSTAGE * SA_STAGE_HALVES + NSTAGE * SB_STAGE_HALVES) * (int)sizeof(__half);
    cudaFuncSetAttribute(gemm_kernel,
                         cudaFuncAttributeMaxDynamicSharedMemorySize, smem_bytes);
    dim3 grid(M_DIM / BM, N_DIM / BN);   // (64, 86)
    gemm_kernel<<<grid, NT, smem_bytes>>>(bias, out);
}